// round 6
// baseline (speedup 1.0000x reference)
#include <cuda_runtime.h>
#include <cstdint>

#define VOCAB  8000
#define VPAD   8064               // padded rows in g_Wo (kept; only first VOCAB used)
#define HIDDEN 256
#define BATCH  32
#define SEQ    256
#define NROW   (SEQ * BATCH)      // 8192 output rows

// ---------------- scratch (device globals: allocation-free) ----------------
__device__ float g_WT[VOCAB * HIDDEN];   // W_ih transposed: [vocab][hidden]
__device__ float g_Xp[NROW * HIDDEN];    // gathered emb + b_ih + b_hh, rows = s*BATCH+b
__device__ float g_Y [NROW * HIDDEN];    // RNN hidden outputs (tf32-rounded)
__device__ float g_Wo[VPAD * HIDDEN];    // W_out pre-rounded to tf32
__device__ float g_hlast[BATCH * HIDDEN];// exact fp32 final hidden state

extern __shared__ unsigned char dynsm[];

// ---------------- helpers ----------------
__device__ __forceinline__ uint32_t smem_u32(const void* p) {
    uint32_t a;
    asm("{ .reg .u64 t; cvta.to.shared.u64 t, %1; cvt.u32.u64 %0, t; }"
        : "=r"(a) : "l"(p));
    return a;
}
__device__ __forceinline__ uint32_t f2tf32(float f) {
    uint32_t r; asm("cvt.rna.tf32.f32 %0, %1;" : "=r"(r) : "f"(f)); return r;
}
__device__ __forceinline__ void fma2(uint64_t& d, uint64_t a, uint64_t b) {
    asm("fma.rn.f32x2 %0, %1, %2, %0;" : "+l"(d) : "l"(a), "l"(b));
}
__device__ __forceinline__ float lo32(uint64_t v) { return __uint_as_float((uint32_t)v); }
__device__ __forceinline__ float hi32(uint64_t v) { return __uint_as_float((uint32_t)(v >> 32)); }
__device__ __forceinline__ void cpa16(uint32_t dst, const void* src) {
    asm volatile("cp.async.cg.shared.global [%0], [%1], 16;" :: "r"(dst), "l"(src));
}

// ---------------- K0: transpose W_ih (HIDDEN x VOCAB) -> g_WT ----------------
__global__ void transpose_wih(const float* __restrict__ W) {
    __shared__ float tile[32][33];
    int vx = blockIdx.x * 32 + threadIdx.x;
    int ib = blockIdx.y * 32;
    #pragma unroll
    for (int k = 0; k < 32; k += 8) {
        int i = ib + threadIdx.y + k;
        tile[threadIdx.y + k][threadIdx.x] = W[(size_t)i * VOCAB + vx];
    }
    __syncthreads();
    int i = ib + threadIdx.x;
    #pragma unroll
    for (int k = 0; k < 32; k += 8) {
        int v = blockIdx.x * 32 + threadIdx.y + k;
        g_WT[(size_t)v * HIDDEN + i] = tile[threadIdx.x][threadIdx.y + k];
    }
}

// ---------------- K1: gather embedding + fold both biases ----------------
__global__ void gather_emb(const int* __restrict__ X,
                           const float* __restrict__ b_ih,
                           const float* __restrict__ b_hh) {
    int idx = blockIdx.x * blockDim.x + threadIdx.x;
    int r = idx >> 6, q = idx & 63;
    int s = r >> 5, b = r & 31;
    int v = X[b * SEQ + s];
    float4 e  = ((const float4*)g_WT)[(size_t)v * 64 + q];
    float4 bi = ((const float4*)b_ih)[q];
    float4 bh = ((const float4*)b_hh)[q];
    e.x += bi.x + bh.x;  e.y += bi.y + bh.y;
    e.z += bi.z + bh.z;  e.w += bi.w + bh.w;
    ((float4*)g_Xp)[(size_t)r * 64 + q] = e;
}

// ---------------- K1b: pre-round W_out to tf32 ----------------
__global__ void round_wout(const float* __restrict__ Wout) {
    int i = blockIdx.x * blockDim.x + threadIdx.x;  // over VOCAB*64 float4s
    float4 f = ((const float4*)Wout)[i];
    uint4 u = make_uint4(f2tf32(f.x), f2tf32(f.y), f2tf32(f.z), f2tf32(f.w));
    ((uint4*)g_Wo)[i] = u;
}

// ---------------- K2: RNN scan v3 (unchanged from R5 — to be measured) ----------------
#define WS_STRIDE 258
#define HB_OFF    (128 * WS_STRIDE)       // hbuf: [2][8][34] floats (part-padded)
#define RNN_SMEM  ((HB_OFF + 2 * 272) * 4)

__global__ void __launch_bounds__(1024, 1)
rnn_scan3(const float* __restrict__ Whh, const float* __restrict__ h0) {
    float* Ws = (float*)dynsm;            // [128][258]
    float* hb = Ws + HB_OFF;              // [2][8][34]

    const int t    = threadIdx.x;
    const int b    = blockIdx.x;
    const int lane = t & 31;
    const int warp = t >> 5;
    const int o    = warp * 4 + (lane >> 3);   // 0..127
    const int p    = lane & 7;                 // K part

    for (int i = t; i < 128 * 256; i += 1024) {
        int r = i >> 8, c = i & 255;
        Ws[r * WS_STRIDE + c] = Whh[r * 256 + c];
    }
    uint64_t wr[16];
    {
        const uint64_t* wsrc = (const uint64_t*)(Whh + (size_t)(128 + o) * 256 + p * 32);
        #pragma unroll
        for (int i = 0; i < 16; i++) wr[i] = wsrc[i];
    }
    if (t < 256) hb[(t >> 5) * 34 + (t & 31)] = h0[b * 256 + t];

    const bool own = (p < 2);
    const int  c   = (p == 0) ? o : (o + 128);
    const float* xptr = g_Xp + (size_t)b * HIDDEN + c;
    float xcur = own ? __ldg(xptr) : 0.f;
    __syncthreads();

    const uint64_t* wss = (const uint64_t*)(Ws + o * WS_STRIDE + p * 32);

    int par = 0;
    for (int s = 0; s < SEQ; s++) {
        if (s > 0 && t < 256) {
            float hv = hb[par * 272 + (t >> 5) * 34 + (t & 31)];
            g_Y[(size_t)((s - 1) * BATCH + b) * HIDDEN + t] = __uint_as_float(f2tf32(hv));
        }
        float xnxt = 0.f;
        if (own && s + 1 < SEQ) xnxt = __ldg(xptr + (size_t)(s + 1) * BATCH * HIDDEN);

        const uint64_t* hsg = (const uint64_t*)(hb + par * 272 + p * 34);
        uint64_t a0 = 0, a1 = 0;
        #pragma unroll
        for (int j = 0; j < 16; j++) {
            uint64_t h2 = hsg[j];
            fma2(a0, wss[j], h2);
            fma2(a1, wr[j],  h2);
        }
        float s0 = lo32(a0) + hi32(a0);
        float s1 = lo32(a1) + hi32(a1);
        #pragma unroll
        for (int m = 4; m; m >>= 1) {
            s0 += __shfl_xor_sync(0xffffffffu, s0, m, 8);
            s1 += __shfl_xor_sync(0xffffffffu, s1, m, 8);
        }
        if (own) {
            float pre = ((p == 0) ? s0 : s1) + xcur;
            float hv  = tanhf(pre);
            hb[(par ^ 1) * 272 + (c >> 5) * 34 + (c & 31)] = hv;
            xcur = xnxt;
        }
        __syncthreads();
        par ^= 1;
    }
    if (t < 256) {
        float hv = hb[par * 272 + (t >> 5) * 34 + (t & 31)];
        g_Y[(size_t)((SEQ - 1) * BATCH + b) * HIDDEN + t] = __uint_as_float(f2tf32(hv));
        g_hlast[b * HIDDEN + t] = hv;
    }
}

// ---------------- K3: output GEMM — reverted to R4-proven BM128 x BN64 ----------------
// out[r][v] = sum_k Y[r][k] * W_out[v][k] + b_out[v]
// 256 threads, 8 warps as 4(M)x2(N); warp tile 32x32 via m16n8k8; 2-stage cp.async.
#define STG_FLOATS (128 * 36 + 64 * 36)   // 6912 u32 per stage
#define GEMM_SMEM  (2 * STG_FLOATS * 4)   // 55296 bytes

__device__ __forceinline__ void mma_tf32(float* d, const uint32_t* a, const uint32_t* b) {
    asm volatile(
        "mma.sync.aligned.m16n8k8.row.col.f32.tf32.tf32.f32 "
        "{%0,%1,%2,%3}, {%4,%5,%6,%7}, {%8,%9}, {%0,%1,%2,%3};"
        : "+f"(d[0]), "+f"(d[1]), "+f"(d[2]), "+f"(d[3])
        : "r"(a[0]), "r"(a[1]), "r"(a[2]), "r"(a[3]), "r"(b[0]), "r"(b[1]));
}

__global__ __launch_bounds__(256)
void gemm_out(const float* __restrict__ bout, float* __restrict__ out) {
    uint32_t* smbase = (uint32_t*)dynsm;
    const int t = threadIdx.x;
    const int warp = t >> 5, lane = t & 31;
    const int wm = warp & 3, wn = warp >> 2;
    const int r = lane >> 2, c = lane & 3;
    const int rowBase = blockIdx.y * 128;
    const int colBase = blockIdx.x * 64;

    const uint32_t sm0 = smem_u32(smbase);

    float acc[2][4][4];
    #pragma unroll
    for (int mt = 0; mt < 2; mt++)
        #pragma unroll
        for (int nt = 0; nt < 4; nt++)
            #pragma unroll
            for (int i = 0; i < 4; i++) acc[mt][nt][i] = 0.f;

    auto load_stage = [&](int kt, int st) {
        uint32_t abase = sm0 + st * (STG_FLOATS * 4);
        uint32_t bbase = abase + 128 * 36 * 4;
        #pragma unroll
        for (int q = 0; q < 4; q++) {          // A: 128x32 from g_Y
            int lin = q * 256 + t;
            int m = lin >> 3, k4 = lin & 7;
            cpa16(abase + (m * 36 + k4 * 4) * 4,
                  g_Y + (size_t)(rowBase + m) * HIDDEN + kt * 32 + k4 * 4);
        }
        #pragma unroll
        for (int q = 0; q < 2; q++) {          // B: 64x32 from g_Wo
            int lin = q * 256 + t;
            int n = lin >> 3, k4 = lin & 7;
            cpa16(bbase + (n * 36 + k4 * 4) * 4,
                  g_Wo + (size_t)(colBase + n) * HIDDEN + kt * 32 + k4 * 4);
        }
        asm volatile("cp.async.commit_group;");
    };

    load_stage(0, 0);

    for (int kt = 0; kt < 8; kt++) {
        if (kt < 7) {
            load_stage(kt + 1, (kt + 1) & 1);
            asm volatile("cp.async.wait_group 1;");
        } else {
            asm volatile("cp.async.wait_group 0;");
        }
        __syncthreads();

        const uint32_t* As = smbase + (kt & 1) * STG_FLOATS;
        const uint32_t* Bs = As + 128 * 36;

        #pragma unroll
        for (int ks = 0; ks < 4; ks++) {
            uint32_t a[2][4], bf[4][2];
            #pragma unroll
            for (int mt = 0; mt < 2; mt++) {
                int mb = wm * 32 + mt * 16;
                a[mt][0] = As[(mb + r    ) * 36 + ks * 8 + c    ];
                a[mt][1] = As[(mb + r + 8) * 36 + ks * 8 + c    ];
                a[mt][2] = As[(mb + r    ) * 36 + ks * 8 + c + 4];
                a[mt][3] = As[(mb + r + 8) * 36 + ks * 8 + c + 4];
            }
            #pragma unroll
            for (int nt = 0; nt < 4; nt++) {
                int nb = wn * 32 + nt * 8 + r;
                bf[nt][0] = Bs[nb * 36 + ks * 8 + c    ];
                bf[nt][1] = Bs[nb * 36 + ks * 8 + c + 4];
            }
            #pragma unroll
            for (int mt = 0; mt < 2; mt++)
                #pragma unroll
                for (int nt = 0; nt < 4; nt++)
                    mma_tf32(acc[mt][nt], a[mt], bf[nt]);
        }
        __syncthreads();
    }

    // epilogue: add bias, STG.64 pairs (VOCAB % 64 == 0 -> no predication needed)
    #pragma unroll
    for (int mt = 0; mt < 2; mt++) {
        int r0 = rowBase + wm * 32 + mt * 16 + r;
        #pragma unroll
        for (int nt = 0; nt < 4; nt++) {
            int col = colBase + wn * 32 + nt * 8 + c * 2;
            float bo0 = bout[col], bo1 = bout[col + 1];
            float2 v0 = make_float2(acc[mt][nt][0] + bo0, acc[mt][nt][1] + bo1);
            float2 v1 = make_float2(acc[mt][nt][2] + bo0, acc[mt][nt][3] + bo1);
            *(float2*)&out[(size_t)r0       * VOCAB + col] = v0;
            *(float2*)&out[(size_t)(r0 + 8) * VOCAB + col] = v1;
        }
    }
}

// ---------------- K4: h_last tail (exact fp32) ----------------
__global__ void tail_copy(float* __restrict__ out) {
    int t = blockIdx.x * blockDim.x + threadIdx.x;   // 0..8191
    out[(size_t)NROW * VOCAB + t] = g_hlast[t];
}

// ---------------- launch ----------------
extern "C" void kernel_launch(void* const* d_in, const int* in_sizes, int n_in,
                              void* d_out, int out_size) {
    const int*   X     = (const int*)  d_in[0];
    const float* h0    = (const float*)d_in[1];
    const float* W_ih  = (const float*)d_in[2];
    const float* b_ih  = (const float*)d_in[3];
    const float* W_hh  = (const float*)d_in[4];
    const float* b_hh  = (const float*)d_in[5];
    const float* W_out = (const float*)d_in[6];
    const float* b_out = (const float*)d_in[7];
    float* out = (float*)d_out;

    cudaFuncSetAttribute(rnn_scan3, cudaFuncAttributeMaxDynamicSharedMemorySize, RNN_SMEM);
    cudaFuncSetAttribute(gemm_out,  cudaFuncAttributeMaxDynamicSharedMemorySize, GEMM_SMEM);

    transpose_wih<<<dim3(VOCAB / 32, HIDDEN / 32), dim3(32, 8)>>>(W_ih);
    gather_emb<<<(NROW * 64) / 256, 256>>>(X, b_ih, b_hh);
    round_wout<<<(VOCAB * 64) / 256, 256>>>(W_out);
    rnn_scan3<<<BATCH, 1024, RNN_SMEM>>>(W_hh, h0);
    gemm_out<<<dim3(VOCAB / 64, NROW / 128), 256, GEMM_SMEM>>>(b_out, out);
    if ((long long)out_size >= (long long)NROW * VOCAB + BATCH * HIDDEN)
        tail_copy<<<BATCH, HIDDEN>>>(out);
}

// round 7
// speedup vs baseline: 2.3948x; 2.3948x over previous
#include <cuda_runtime.h>
#include <cstdint>

#define VOCAB  8000
#define VPAD   8064               // padded rows in g_Wo (kept; only first VOCAB used)
#define HIDDEN 256
#define BATCH  32
#define SEQ    256
#define NROW   (SEQ * BATCH)      // 8192 output rows

// ---------------- scratch (device globals: allocation-free) ----------------
__device__ float g_WT[VOCAB * HIDDEN];   // W_ih transposed: [vocab][hidden]
__device__ float g_Xp[NROW * HIDDEN];    // gathered emb + b_ih + b_hh, rows = s*BATCH+b
__device__ float g_Y [NROW * HIDDEN];    // RNN hidden outputs (tf32-rounded)
__device__ float g_Wo[VPAD * HIDDEN];    // W_out pre-rounded to tf32
__device__ float g_hlast[BATCH * HIDDEN];// exact fp32 final hidden state

extern __shared__ unsigned char dynsm[];

// ---------------- helpers ----------------
__device__ __forceinline__ uint32_t smem_u32(const void* p) {
    uint32_t a;
    asm("{ .reg .u64 t; cvta.to.shared.u64 t, %1; cvt.u32.u64 %0, t; }"
        : "=r"(a) : "l"(p));
    return a;
}
__device__ __forceinline__ uint32_t f2tf32(float f) {
    uint32_t r; asm("cvt.rna.tf32.f32 %0, %1;" : "=r"(r) : "f"(f)); return r;
}
__device__ __forceinline__ void fma2(uint64_t& d, uint64_t a, uint64_t b) {
    asm("fma.rn.f32x2 %0, %1, %2, %0;" : "+l"(d) : "l"(a), "l"(b));
}
__device__ __forceinline__ float lo32(uint64_t v) { return __uint_as_float((uint32_t)v); }
__device__ __forceinline__ float hi32(uint64_t v) { return __uint_as_float((uint32_t)(v >> 32)); }
__device__ __forceinline__ void cpa16(uint32_t dst, const void* src) {
    asm volatile("cp.async.cg.shared.global [%0], [%1], 16;" :: "r"(dst), "l"(src));
}

// ---------------- K0: transpose W_ih (HIDDEN x VOCAB) -> g_WT ----------------
__global__ void transpose_wih(const float* __restrict__ W) {
    __shared__ float tile[32][33];
    int vx = blockIdx.x * 32 + threadIdx.x;
    int ib = blockIdx.y * 32;
    #pragma unroll
    for (int k = 0; k < 32; k += 8) {
        int i = ib + threadIdx.y + k;
        tile[threadIdx.y + k][threadIdx.x] = W[(size_t)i * VOCAB + vx];
    }
    __syncthreads();
    int i = ib + threadIdx.x;
    #pragma unroll
    for (int k = 0; k < 32; k += 8) {
        int v = blockIdx.x * 32 + threadIdx.y + k;
        g_WT[(size_t)v * HIDDEN + i] = tile[threadIdx.x][threadIdx.y + k];
    }
}

// ---------------- K1: gather embedding + fold both biases ----------------
__global__ void gather_emb(const int* __restrict__ X,
                           const float* __restrict__ b_ih,
                           const float* __restrict__ b_hh) {
    int idx = blockIdx.x * blockDim.x + threadIdx.x;
    int r = idx >> 6, q = idx & 63;
    int s = r >> 5, b = r & 31;
    int v = X[b * SEQ + s];
    float4 e  = ((const float4*)g_WT)[(size_t)v * 64 + q];
    float4 bi = ((const float4*)b_ih)[q];
    float4 bh = ((const float4*)b_hh)[q];
    e.x += bi.x + bh.x;  e.y += bi.y + bh.y;
    e.z += bi.z + bh.z;  e.w += bi.w + bh.w;
    ((float4*)g_Xp)[(size_t)r * 64 + q] = e;
}

// ---------------- K1b: pre-round W_out to tf32 ----------------
__global__ void round_wout(const float* __restrict__ Wout) {
    int i = blockIdx.x * blockDim.x + threadIdx.x;  // over VOCAB*64 float4s
    float4 f = ((const float4*)Wout)[i];
    uint4 u = make_uint4(f2tf32(f.x), f2tf32(f.y), f2tf32(f.z), f2tf32(f.w));
    ((uint4*)g_Wo)[i] = u;
}

// ---------------- K2: RNN scan v4 — scan3 structure, conflict-free W layout ----------------
// 32 CTAs (one batch each), 1024 threads. o = warp*4 + (lane>>3), p = lane&7.
// W smem half stored part-padded: Ws[o][p-seg] at o*272 + p*34 (+2j words).
// Bank for (o,p,j) = 16*(o&1) + 2p + 2j mod 32 -> each LDS.64 phase (2 o x 8 p)
// covers all 32 banks exactly once: conflict-free (scan3's p*32 stride was
// 8-way conflicted -> the R5/R6 1.2ms regression).
#define WROW      272                      // 8 * 34 floats per W row
#define HB_OFF    (128 * WROW)             // hbuf: [2][8][34] floats
#define RNN_SMEM  ((HB_OFF + 2 * WROW) * 4)   // 141,440 B

__global__ void __launch_bounds__(1024, 1)
rnn_scan4(const float* __restrict__ Whh, const float* __restrict__ h0) {
    float* Ws = (float*)dynsm;            // [128][8][34]
    float* hb = Ws + HB_OFF;              // [2][8][34]

    const int t    = threadIdx.x;
    const int b    = blockIdx.x;
    const int lane = t & 31;
    const int warp = t >> 5;
    const int o    = warp * 4 + (lane >> 3);   // 0..127
    const int p    = lane & 7;                 // K part

    // fill SMEM half of W (rows 0..127), part-padded layout
    for (int i = t; i < 128 * 256; i += 1024) {
        int r = i >> 8, c = i & 255;
        Ws[r * WROW + (c >> 5) * 34 + (c & 31)] = Whh[r * 256 + c];
    }
    // register half of W: row 128+o, cols [p*32, p*32+32)
    uint64_t wr[16];
    {
        const uint64_t* wsrc = (const uint64_t*)(Whh + (size_t)(128 + o) * 256 + p * 32);
        #pragma unroll
        for (int i = 0; i < 16; i++) wr[i] = wsrc[i];
    }
    // init h0 into parity-0 buffer (part-padded layout)
    if (t < 256) hb[(t >> 5) * 34 + (t & 31)] = h0[b * 256 + t];

    const bool own = (p < 2);
    const int  c   = (p == 0) ? o : (o + 128);
    const float* xptr = g_Xp + (size_t)b * HIDDEN + c;
    float xcur = own ? __ldg(xptr) : 0.f;
    __syncthreads();

    const uint64_t* wss = (const uint64_t*)(Ws + o * WROW + p * 34);

    int par = 0;
    for (int s = 0; s < SEQ; s++) {
        // emit Y row s-1 with otherwise-idle lanes, off the critical path
        if (s > 0 && t < 256) {
            float hv = hb[par * WROW + (t >> 5) * 34 + (t & 31)];
            g_Y[(size_t)((s - 1) * BATCH + b) * HIDDEN + t] = __uint_as_float(f2tf32(hv));
        }
        // prefetch next step's x (addresses independent of h)
        float xnxt = 0.f;
        if (own && s + 1 < SEQ) xnxt = __ldg(xptr + (size_t)(s + 1) * BATCH * HIDDEN);

        // partial dot products (smem half + register half)
        const uint64_t* hsg = (const uint64_t*)(hb + par * WROW + p * 34);
        uint64_t a0 = 0, a1 = 0;
        #pragma unroll
        for (int j = 0; j < 16; j++) {
            uint64_t h2 = hsg[j];      // broadcast across the 4 o's sharing p
            fma2(a0, wss[j], h2);
            fma2(a1, wr[j],  h2);
        }
        float s0 = lo32(a0) + hi32(a0);
        float s1 = lo32(a1) + hi32(a1);
        #pragma unroll
        for (int m = 4; m; m >>= 1) {
            s0 += __shfl_xor_sync(0xffffffffu, s0, m, 8);
            s1 += __shfl_xor_sync(0xffffffffu, s1, m, 8);
        }
        if (own) {
            float pre = ((p == 0) ? s0 : s1) + xcur;
            float hv  = tanhf(pre);
            hb[(par ^ 1) * WROW + (c >> 5) * 34 + (c & 31)] = hv;
            xcur = xnxt;
        }
        __syncthreads();
        par ^= 1;
    }
    // final: Y row SEQ-1 and exact h_last
    if (t < 256) {
        float hv = hb[par * WROW + (t >> 5) * 34 + (t & 31)];
        g_Y[(size_t)((SEQ - 1) * BATCH + b) * HIDDEN + t] = __uint_as_float(f2tf32(hv));
        g_hlast[b * HIDDEN + t] = hv;
    }
}

// ---------------- K3: output GEMM — R4-proven BM128 x BN64 (unchanged) ----------------
// out[r][v] = sum_k Y[r][k] * W_out[v][k] + b_out[v]
// 256 threads, 8 warps as 4(M)x2(N); warp tile 32x32 via m16n8k8; 2-stage cp.async.
#define STG_FLOATS (128 * 36 + 64 * 36)   // 6912 u32 per stage
#define GEMM_SMEM  (2 * STG_FLOATS * 4)   // 55296 bytes

__device__ __forceinline__ void mma_tf32(float* d, const uint32_t* a, const uint32_t* b) {
    asm volatile(
        "mma.sync.aligned.m16n8k8.row.col.f32.tf32.tf32.f32 "
        "{%0,%1,%2,%3}, {%4,%5,%6,%7}, {%8,%9}, {%0,%1,%2,%3};"
        : "+f"(d[0]), "+f"(d[1]), "+f"(d[2]), "+f"(d[3])
        : "r"(a[0]), "r"(a[1]), "r"(a[2]), "r"(a[3]), "r"(b[0]), "r"(b[1]));
}

__global__ __launch_bounds__(256)
void gemm_out(const float* __restrict__ bout, float* __restrict__ out) {
    uint32_t* smbase = (uint32_t*)dynsm;
    const int t = threadIdx.x;
    const int warp = t >> 5, lane = t & 31;
    const int wm = warp & 3, wn = warp >> 2;
    const int r = lane >> 2, c = lane & 3;
    const int rowBase = blockIdx.y * 128;
    const int colBase = blockIdx.x * 64;

    const uint32_t sm0 = smem_u32(smbase);

    float acc[2][4][4];
    #pragma unroll
    for (int mt = 0; mt < 2; mt++)
        #pragma unroll
        for (int nt = 0; nt < 4; nt++)
            #pragma unroll
            for (int i = 0; i < 4; i++) acc[mt][nt][i] = 0.f;

    auto load_stage = [&](int kt, int st) {
        uint32_t abase = sm0 + st * (STG_FLOATS * 4);
        uint32_t bbase = abase + 128 * 36 * 4;
        #pragma unroll
        for (int q = 0; q < 4; q++) {          // A: 128x32 from g_Y
            int lin = q * 256 + t;
            int m = lin >> 3, k4 = lin & 7;
            cpa16(abase + (m * 36 + k4 * 4) * 4,
                  g_Y + (size_t)(rowBase + m) * HIDDEN + kt * 32 + k4 * 4);
        }
        #pragma unroll
        for (int q = 0; q < 2; q++) {          // B: 64x32 from g_Wo
            int lin = q * 256 + t;
            int n = lin >> 3, k4 = lin & 7;
            cpa16(bbase + (n * 36 + k4 * 4) * 4,
                  g_Wo + (size_t)(colBase + n) * HIDDEN + kt * 32 + k4 * 4);
        }
        asm volatile("cp.async.commit_group;");
    };

    load_stage(0, 0);

    for (int kt = 0; kt < 8; kt++) {
        if (kt < 7) {
            load_stage(kt + 1, (kt + 1) & 1);
            asm volatile("cp.async.wait_group 1;");
        } else {
            asm volatile("cp.async.wait_group 0;");
        }
        __syncthreads();

        const uint32_t* As = smbase + (kt & 1) * STG_FLOATS;
        const uint32_t* Bs = As + 128 * 36;

        #pragma unroll
        for (int ks = 0; ks < 4; ks++) {
            uint32_t a[2][4], bf[4][2];
            #pragma unroll
            for (int mt = 0; mt < 2; mt++) {
                int mb = wm * 32 + mt * 16;
                a[mt][0] = As[(mb + r    ) * 36 + ks * 8 + c    ];
                a[mt][1] = As[(mb + r + 8) * 36 + ks * 8 + c    ];
                a[mt][2] = As[(mb + r    ) * 36 + ks * 8 + c + 4];
                a[mt][3] = As[(mb + r + 8) * 36 + ks * 8 + c + 4];
            }
            #pragma unroll
            for (int nt = 0; nt < 4; nt++) {
                int nb = wn * 32 + nt * 8 + r;
                bf[nt][0] = Bs[nb * 36 + ks * 8 + c    ];
                bf[nt][1] = Bs[nb * 36 + ks * 8 + c + 4];
            }
            #pragma unroll
            for (int mt = 0; mt < 2; mt++)
                #pragma unroll
                for (int nt = 0; nt < 4; nt++)
                    mma_tf32(acc[mt][nt], a[mt], bf[nt]);
        }
        __syncthreads();
    }

    // epilogue: add bias, STG.64 pairs (VOCAB % 64 == 0 -> no predication needed)
    #pragma unroll
    for (int mt = 0; mt < 2; mt++) {
        int r0 = rowBase + wm * 32 + mt * 16 + r;
        #pragma unroll
        for (int nt = 0; nt < 4; nt++) {
            int col = colBase + wn * 32 + nt * 8 + c * 2;
            float bo0 = bout[col], bo1 = bout[col + 1];
            float2 v0 = make_float2(acc[mt][nt][0] + bo0, acc[mt][nt][1] + bo1);
            float2 v1 = make_float2(acc[mt][nt][2] + bo0, acc[mt][nt][3] + bo1);
            *(float2*)&out[(size_t)r0       * VOCAB + col] = v0;
            *(float2*)&out[(size_t)(r0 + 8) * VOCAB + col] = v1;
        }
    }
}

// ---------------- K4: h_last tail (exact fp32) ----------------
__global__ void tail_copy(float* __restrict__ out) {
    int t = blockIdx.x * blockDim.x + threadIdx.x;   // 0..8191
    out[(size_t)NROW * VOCAB + t] = g_hlast[t];
}

// ---------------- launch ----------------
extern "C" void kernel_launch(void* const* d_in, const int* in_sizes, int n_in,
                              void* d_out, int out_size) {
    const int*   X     = (const int*)  d_in[0];
    const float* h0    = (const float*)d_in[1];
    const float* W_ih  = (const float*)d_in[2];
    const float* b_ih  = (const float*)d_in[3];
    const float* W_hh  = (const float*)d_in[4];
    const float* b_hh  = (const float*)d_in[5];
    const float* W_out = (const float*)d_in[6];
    const float* b_out = (const float*)d_in[7];
    float* out = (float*)d_out;

    cudaFuncSetAttribute(rnn_scan4, cudaFuncAttributeMaxDynamicSharedMemorySize, RNN_SMEM);
    cudaFuncSetAttribute(gemm_out,  cudaFuncAttributeMaxDynamicSharedMemorySize, GEMM_SMEM);

    transpose_wih<<<dim3(VOCAB / 32, HIDDEN / 32), dim3(32, 8)>>>(W_ih);
    gather_emb<<<(NROW * 64) / 256, 256>>>(X, b_ih, b_hh);
    round_wout<<<(VOCAB * 64) / 256, 256>>>(W_out);
    rnn_scan4<<<BATCH, 1024, RNN_SMEM>>>(W_hh, h0);
    gemm_out<<<dim3(VOCAB / 64, NROW / 128), 256, GEMM_SMEM>>>(b_out, out);
    if ((long long)out_size >= (long long)NROW * VOCAB + BATCH * HIDDEN)
        tail_copy<<<BATCH, HIDDEN>>>(out);
}